// round 2
// baseline (speedup 1.0000x reference)
#include <cuda_runtime.h>
#include <math.h>

// ---------------- problem constants ----------------
#define BATCH   2
#define LTXT    256
#define NIMG    2048
#define NTOK    2304          // LTXT + NIMG
#define DMODEL  1536
#define NH      12
#define DHEAD   128
#define TD      4608          // 3*DMODEL (qkv width / mod width)
#define MLPH    6144
#define ROWS    (BATCH*NTOK)  // 4608

// ---------------- device scratch (no allocs allowed) ----------------
__device__ __align__(128) float g_x   [ROWS*DMODEL];   // residual stream
__device__ __align__(128) float g_xn  [ROWS*DMODEL];   // normed/modulated
__device__ __align__(128) float g_qkv [ROWS*TD];
__device__ __align__(128) float g_q   [ROWS*DMODEL];   // (B,H,N,DH)
__device__ __align__(128) float g_k   [ROWS*DMODEL];
__device__ __align__(128) float g_v   [ROWS*DMODEL];
__device__ __align__(128) float g_attn[ROWS*DMODEL];   // (B,N,H*DH)
__device__ __align__(128) float g_h   [ROWS*MLPH];
__device__ __align__(128) float g_mod [BATCH*TD];      // shift|scale|gate per batch

// ---------------- helpers ----------------
__device__ __forceinline__ float blockReduceSum256(float v, float* red) {
    int tid = threadIdx.x;
    red[tid] = v;
    __syncthreads();
    #pragma unroll
    for (int s = 128; s > 0; s >>= 1) {
        if (tid < s) red[tid] += red[tid + s];
        __syncthreads();
    }
    return red[0];
}

__device__ __forceinline__ float gelu_tanh(float x) {
    float x3 = x * x * x;
    return 0.5f * x * (1.f + tanhf(0.7978845608028654f * (x + 0.044715f * x3)));
}

// ---------------- K1: modulation  emb = silu(vec) @ w_mod^T + b_mod ----------------
__global__ void __launch_bounds__(256) mod_kernel(
    const float* __restrict__ vec, const float* __restrict__ wmod,
    const float* __restrict__ bmod)
{
    __shared__ float red[256];
    int o = blockIdx.x;                 // 0 .. BATCH*TD-1
    int b = o / TD;
    int j = o - b * TD;
    const float* v = vec + b * DMODEL;
    const float* w = wmod + (size_t)j * DMODEL;
    float s = 0.f;
    for (int i = threadIdx.x; i < DMODEL; i += 256) {
        float x = v[i];
        s += (x / (1.f + __expf(-x))) * w[i];
    }
    s = blockReduceSum256(s, red);
    if (threadIdx.x == 0) g_mod[o] = s + bmod[j];
}

// ---------------- K2: concat + RMSNorm (+ optional AdaLN modulate) ----------------
template<bool MOD1>
__global__ void __launch_bounds__(256) norm_kernel(
    const float* __restrict__ txt, const float* __restrict__ img,
    const float* __restrict__ w)
{
    __shared__ float red[256];
    int r = blockIdx.x;
    int b = r / NTOK;
    int n = r - b * NTOK;
    float* xrow = g_x + (size_t)r * DMODEL;
    const float* src;
    if (MOD1) {
        src = (n < LTXT) ? txt + (size_t)(b * LTXT + n) * DMODEL
                         : img + (size_t)(b * NIMG + n - LTXT) * DMODEL;
    } else {
        src = xrow;
    }
    float ss = 0.f;
    for (int i = threadIdx.x; i < DMODEL; i += 256) {
        float v = src[i];
        if (MOD1) xrow[i] = v;
        ss += v * v;
    }
    ss = blockReduceSum256(ss, red);
    float inv = rsqrtf(ss * (1.f / DMODEL) + 1e-6f);
    float* dst = g_xn + (size_t)r * DMODEL;
    if (MOD1) {
        const float* shift = g_mod + b * TD;
        const float* scale = shift + DMODEL;
        for (int i = threadIdx.x; i < DMODEL; i += 256)
            dst[i] = xrow[i] * inv * w[i] * (1.f + scale[i]) + shift[i];
    } else {
        for (int i = threadIdx.x; i < DMODEL; i += 256)
            dst[i] = src[i] * inv * w[i];
    }
}

// ---------------- K3: generic tiled GEMM  C = A(M,K) @ Bw(Nc,K)^T  + epilogue ----------------
// EPI 0: plain store           (qkv)
// EPI 1: gelu(acc + bias)      (fc1)
// EPI 2: res + gate*acc        (out-proj, in-place into g_x; gate = mod[b][2D+col])
// EPI 3: acc + bias + res, scatter to split txt/img output   (fc2)
template<int EPI>
__global__ void __launch_bounds__(256) gemm_kernel(
    const float* __restrict__ A, const float* __restrict__ Bw,
    float* __restrict__ C, int M, int Nc, int K,
    const float* __restrict__ bias, const float* __restrict__ res,
    const float* __restrict__ modv, float* __restrict__ outp)
{
    __shared__ float As[8][128];
    __shared__ float Bs[8][128];

    int tid = threadIdx.x;
    int tx = tid & 15, ty = tid >> 4;        // 16 x 16 thread tile
    int mBase = blockIdx.y * 128;
    int nBase = blockIdx.x * 128;

    float acc[8][8];
    #pragma unroll
    for (int i = 0; i < 8; ++i)
        #pragma unroll
        for (int j = 0; j < 8; ++j) acc[i][j] = 0.f;

    int ldRow  = tid >> 1;                   // 0..127
    int ldCol  = (tid & 1) * 4;              // 0 or 4
    const float* Aptr = A  + (size_t)(mBase + ldRow) * K + ldCol;
    const float* Bptr = Bw + (size_t)(nBase + ldRow) * K + ldCol;

    float4 av = *(const float4*)(Aptr);
    float4 bv = *(const float4*)(Bptr);

    for (int k0 = 0; k0 < K; k0 += 8) {
        __syncthreads();   // previous compute done
        As[ldCol+0][ldRow] = av.x; As[ldCol+1][ldRow] = av.y;
        As[ldCol+2][ldRow] = av.z; As[ldCol+3][ldRow] = av.w;
        Bs[ldCol+0][ldRow] = bv.x; Bs[ldCol+1][ldRow] = bv.y;
        Bs[ldCol+2][ldRow] = bv.z; Bs[ldCol+3][ldRow] = bv.w;
        __syncthreads();
        if (k0 + 8 < K) {   // prefetch next k-slab (hides GMEM latency behind compute)
            av = *(const float4*)(Aptr + k0 + 8);
            bv = *(const float4*)(Bptr + k0 + 8);
        }
        #pragma unroll
        for (int k = 0; k < 8; ++k) {
            float a[8], b[8];
            *(float4*)(a)     = *(const float4*)&As[k][ty*8];
            *(float4*)(a + 4) = *(const float4*)&As[k][ty*8 + 4];
            *(float4*)(b)     = *(const float4*)&Bs[k][tx*8];
            *(float4*)(b + 4) = *(const float4*)&Bs[k][tx*8 + 4];
            #pragma unroll
            for (int i = 0; i < 8; ++i)
                #pragma unroll
                for (int j = 0; j < 8; ++j)
                    acc[i][j] = fmaf(a[i], b[j], acc[i][j]);
        }
    }

    // epilogue
    int row0 = mBase + ty * 8;
    int col0 = nBase + tx * 8;
    #pragma unroll
    for (int i = 0; i < 8; ++i) {
        int row = row0 + i;
        int b_idx = row / NTOK;
        int n_idx = row - b_idx * NTOK;
        #pragma unroll
        for (int g = 0; g < 2; ++g) {
            float4 v;
            float* vp = &v.x;
            #pragma unroll
            for (int j = 0; j < 4; ++j) {
                int col = col0 + g * 4 + j;
                float a = acc[i][g * 4 + j];
                if (EPI == 1) {
                    a = gelu_tanh(a + bias[col]);
                } else if (EPI == 2) {
                    a = res[(size_t)row * Nc + col]
                        + modv[b_idx * TD + 2 * DMODEL + col] * a;
                } else if (EPI == 3) {
                    a = a + bias[col] + res[(size_t)row * Nc + col];
                }
                vp[j] = a;
            }
            if (EPI == 3) {
                float* dst = (n_idx < LTXT)
                    ? outp + ((size_t)(b_idx * LTXT + n_idx) * DMODEL + col0 + g * 4)
                    : outp + ((size_t)(BATCH * LTXT * DMODEL)
                              + (size_t)(b_idx * NIMG + n_idx - LTXT) * DMODEL + col0 + g * 4);
                *(float4*)dst = v;
            } else {
                *(float4*)&C[(size_t)row * Nc + col0 + g * 4] = v;
            }
        }
    }
}

// ---------------- K4: RoPE + transpose qkv -> (B,H,N,DH) q/k/v ----------------
__global__ void __launch_bounds__(64) rope_kernel(const float* __restrict__ img_rope)
{
    int r = blockIdx.x;                 // token row 0..ROWS-1
    int b = r / NTOK;
    int n = r - b * NTOK;
    int h = blockIdx.y;
    int t = threadIdx.x;                // pair index 0..63

    float cs = 0.f, sn = 0.f;           // txt positions get zero rope (exactly as ref)
    if (n >= LTXT) {
        const float* rp = img_rope + (size_t)(b * NIMG + n - LTXT) * DHEAD + 2 * t;
        cs = rp[0]; sn = rp[1];
    }
    const float* row = g_qkv + (size_t)r * TD;
    float2 q = *(const float2*)&row[h * DHEAD + 2 * t];
    float2 k = *(const float2*)&row[DMODEL + h * DHEAD + 2 * t];
    float2 v = *(const float2*)&row[2 * DMODEL + h * DHEAD + 2 * t];

    size_t o = ((size_t)(b * NH + h) * NTOK + n) * DHEAD + 2 * t;
    float2 qo = make_float2(q.x * cs - q.y * sn, q.y * cs + q.x * sn);
    float2 ko = make_float2(k.x * cs - k.y * sn, k.y * cs + k.x * sn);
    *(float2*)&g_q[o] = qo;
    *(float2*)&g_k[o] = ko;
    *(float2*)&g_v[o] = v;
}

// ---------------- K5: flash attention, fp32, 64x64 tiles ----------------
#define BQ  64
#define BKV 64
#define KT_STRIDE 68          // padded transposed-K row stride (float4-aligned, 2-way max)
#define SS_STRIDE 65
#define ATT_SMEM_FLOATS (BQ*DHEAD + DHEAD*KT_STRIDE + BKV*DHEAD + BQ*SS_STRIDE + 3*BQ)
#define ATT_SMEM_BYTES  (ATT_SMEM_FLOATS * 4)

__global__ void __launch_bounds__(256) attn_kernel()
{
    extern __shared__ float sm[];
    float* Qs   = sm;                           // [64][128]
    float* Kts  = Qs  + BQ * DHEAD;             // [128][68] transposed K
    float* Vs   = Kts + DHEAD * KT_STRIDE;      // [64][128]
    float* Ss   = Vs  + BKV * DHEAD;            // [64][65]
    float* rowm = Ss  + BQ * SS_STRIDE;
    float* rowl = rowm + BQ;
    float* rowc = rowl + BQ;

    int tid = threadIdx.x;
    int bh  = blockIdx.y;                       // 0..B*H-1
    int b   = bh / NH;
    int h   = bh - b * NH;
    int q0  = blockIdx.x * BQ;

    const float* Qg = g_q + ((size_t)bh * NTOK + q0) * DHEAD;
    const float* Kg = g_k + (size_t)bh * NTOK * DHEAD;
    const float* Vg = g_v + (size_t)bh * NTOK * DHEAD;

    // load Q tile
    #pragma unroll
    for (int it = 0; it < 8; ++it) {
        int f = it * 256 + tid;                 // float4 id, 0..2047
        int n = f >> 5;
        int k4 = (f & 31) * 4;
        *(float4*)&Qs[n * DHEAD + k4] = *(const float4*)&Qg[n * DHEAD + k4];
    }
    if (tid < BQ) { rowm[tid] = -1e30f; rowl[tid] = 0.f; }

    float Oacc[32];
    #pragma unroll
    for (int i = 0; i < 32; ++i) Oacc[i] = 0.f;
    int orow = tid & 63;
    int ocb  = (tid >> 6) * 32;
    int tx = tid & 15, ty = tid >> 4;
    __syncthreads();

    const float scale = 0.08838834764831845f;   // DH^-0.5

    for (int t = 0; t < NTOK / BKV; ++t) {
        const float* Kt = Kg + (size_t)t * BKV * DHEAD;
        const float* Vt = Vg + (size_t)t * BKV * DHEAD;
        #pragma unroll
        for (int it = 0; it < 8; ++it) {
            int f = it * 256 + tid;
            int n = f >> 5;
            int k4 = (f & 31) * 4;
            float4 kv = *(const float4*)&Kt[n * DHEAD + k4];
            Kts[(k4 + 0) * KT_STRIDE + n] = kv.x;
            Kts[(k4 + 1) * KT_STRIDE + n] = kv.y;
            Kts[(k4 + 2) * KT_STRIDE + n] = kv.z;
            Kts[(k4 + 3) * KT_STRIDE + n] = kv.w;
            *(float4*)&Vs[n * DHEAD + k4] = *(const float4*)&Vt[n * DHEAD + k4];
        }
        __syncthreads();

        // S(64x64) = Q K^T : each thread 4x4
        float s[4][4];
        #pragma unroll
        for (int i = 0; i < 4; ++i)
            #pragma unroll
            for (int j = 0; j < 4; ++j) s[i][j] = 0.f;

        for (int k = 0; k < DHEAD; k += 4) {
            float avr[4][4];
            #pragma unroll
            for (int i = 0; i < 4; ++i) {
                float4 a4 = *(const float4*)&Qs[(ty * 4 + i) * DHEAD + k];
                avr[i][0] = a4.x; avr[i][1] = a4.y; avr[i][2] = a4.z; avr[i][3] = a4.w;
            }
            #pragma unroll
            for (int kk = 0; kk < 4; ++kk) {
                float4 bv = *(const float4*)&Kts[(k + kk) * KT_STRIDE + tx * 4];
                #pragma unroll
                for (int i = 0; i < 4; ++i) {
                    float a = avr[i][kk];
                    s[i][0] = fmaf(a, bv.x, s[i][0]);
                    s[i][1] = fmaf(a, bv.y, s[i][1]);
                    s[i][2] = fmaf(a, bv.z, s[i][2]);
                    s[i][3] = fmaf(a, bv.w, s[i][3]);
                }
            }
        }
        #pragma unroll
        for (int i = 0; i < 4; ++i)
            #pragma unroll
            for (int j = 0; j < 4; ++j)
                Ss[(ty * 4 + i) * SS_STRIDE + tx * 4 + j] = s[i][j] * scale;
        __syncthreads();

        // online softmax per row (threads 0..63)
        if (tid < BQ) {
            int r = tid;
            float m = rowm[r];
            float mx = m;
            #pragma unroll 8
            for (int j = 0; j < BKV; ++j) mx = fmaxf(mx, Ss[r * SS_STRIDE + j]);
            float c = __expf(m - mx);
            float l = rowl[r] * c;
            #pragma unroll 8
            for (int j = 0; j < BKV; ++j) {
                float p = __expf(Ss[r * SS_STRIDE + j] - mx);
                Ss[r * SS_STRIDE + j] = p;
                l += p;
            }
            rowm[r] = mx; rowl[r] = l; rowc[r] = c;
        }
        __syncthreads();

        // O = O*c + P @ V  (each thread: 1 row x 32 cols)
        float c = rowc[orow];
        #pragma unroll
        for (int i = 0; i < 32; ++i) Oacc[i] *= c;
        for (int j = 0; j < BKV; ++j) {
            float p = Ss[orow * SS_STRIDE + j];
            const float* vrow = &Vs[j * DHEAD + ocb];
            #pragma unroll
            for (int i = 0; i < 32; i += 4) {
                float4 vv = *(const float4*)&vrow[i];
                Oacc[i + 0] = fmaf(p, vv.x, Oacc[i + 0]);
                Oacc[i + 1] = fmaf(p, vv.y, Oacc[i + 1]);
                Oacc[i + 2] = fmaf(p, vv.z, Oacc[i + 2]);
                Oacc[i + 3] = fmaf(p, vv.w, Oacc[i + 3]);
            }
        }
        __syncthreads();   // before next tile overwrites Kts/Vs/Ss
    }

    float inv = 1.f / rowl[orow];
    float* og = g_attn + (size_t)(b * NTOK + q0 + orow) * DMODEL + h * DHEAD + ocb;
    #pragma unroll
    for (int i = 0; i < 32; i += 4) {
        float4 v = make_float4(Oacc[i] * inv, Oacc[i+1] * inv, Oacc[i+2] * inv, Oacc[i+3] * inv);
        *(float4*)&og[i] = v;
    }
}

// ---------------- host launcher ----------------
extern "C" void kernel_launch(void* const* d_in, const int* in_sizes, int n_in,
                              void* d_out, int out_size)
{
    const float* txt      = (const float*)d_in[0];
    const float* img      = (const float*)d_in[1];
    const float* vec      = (const float*)d_in[2];
    // d_in[3] = txt_rope (ignored, as in reference)
    const float* img_rope = (const float*)d_in[4];
    const float* w_norm1  = (const float*)d_in[5];
    const float* w_mod    = (const float*)d_in[6];
    const float* b_mod    = (const float*)d_in[7];
    const float* w_qkv    = (const float*)d_in[8];
    const float* w_out    = (const float*)d_in[9];
    const float* w_norm2  = (const float*)d_in[10];
    const float* w_fc1    = (const float*)d_in[11];
    const float* b_fc1    = (const float*)d_in[12];
    const float* w_fc2    = (const float*)d_in[13];
    const float* b_fc2    = (const float*)d_in[14];
    float* out = (float*)d_out;

    float *px, *pxn, *pqkv, *pattn, *ph, *pmod;
    cudaGetSymbolAddress((void**)&px,    g_x);
    cudaGetSymbolAddress((void**)&pxn,   g_xn);
    cudaGetSymbolAddress((void**)&pqkv,  g_qkv);
    cudaGetSymbolAddress((void**)&pattn, g_attn);
    cudaGetSymbolAddress((void**)&ph,    g_h);
    cudaGetSymbolAddress((void**)&pmod,  g_mod);

    // 1. AdaLN modulation vector
    mod_kernel<<<BATCH * TD, 256>>>(vec, w_mod, b_mod);
    // 2. concat + RMSNorm + modulate
    norm_kernel<true><<<ROWS, 256>>>(txt, img, w_norm1);
    // 3. qkv projection
    gemm_kernel<0><<<dim3(TD / 128, ROWS / 128), 256>>>(
        pxn, w_qkv, pqkv, ROWS, TD, DMODEL, nullptr, nullptr, nullptr, nullptr);
    // 4. RoPE + head transpose
    rope_kernel<<<dim3(ROWS, NH), 64>>>(img_rope);
    // 5. flash attention
    cudaFuncSetAttribute(attn_kernel, cudaFuncAttributeMaxDynamicSharedMemorySize,
                         ATT_SMEM_BYTES);
    attn_kernel<<<dim3(NTOK / BQ, BATCH * NH), 256, ATT_SMEM_BYTES>>>();
    // 6. out projection + gated residual (in-place into g_x)
    gemm_kernel<2><<<dim3(DMODEL / 128, ROWS / 128), 256>>>(
        pattn, w_out, px, ROWS, DMODEL, DMODEL, nullptr, px, pmod, nullptr);
    // 7. RMSNorm 2
    norm_kernel<false><<<ROWS, 256>>>(nullptr, nullptr, w_norm2);
    // 8. fc1 + gelu
    gemm_kernel<1><<<dim3(MLPH / 128, ROWS / 128), 256>>>(
        pxn, w_fc1, ph, ROWS, MLPH, DMODEL, b_fc1, nullptr, nullptr, nullptr);
    // 9. fc2 + bias + residual, scatter to split txt/img output
    gemm_kernel<3><<<dim3(DMODEL / 128, ROWS / 128), 256>>>(
        ph, w_fc2, nullptr, ROWS, DMODEL, MLPH, b_fc2, px, nullptr, out);
}

// round 4
// speedup vs baseline: 1.7097x; 1.7097x over previous
#include <cuda_runtime.h>
#include <math.h>
#include <stdint.h>

// ---------------- problem constants ----------------
#define BATCH   2
#define LTXT    256
#define NIMG    2048
#define NTOK    2304          // LTXT + NIMG
#define DMODEL  1536
#define NH      12
#define DHEAD   128
#define TD      4608          // 3*DMODEL
#define MLPH    6144
#define ROWS    (BATCH*NTOK)  // 4608

// ---------------- device scratch (no allocs allowed) ----------------
__device__ __align__(128) float g_x   [ROWS*DMODEL];
__device__ __align__(128) float g_xn  [ROWS*DMODEL];
__device__ __align__(128) float g_qkv [ROWS*TD];
__device__ __align__(128) float g_q   [ROWS*DMODEL];
__device__ __align__(128) float g_k   [ROWS*DMODEL];
__device__ __align__(128) float g_v   [ROWS*DMODEL];
__device__ __align__(128) float g_attn[ROWS*DMODEL];
__device__ __align__(128) float g_h   [ROWS*MLPH];
__device__ __align__(128) float g_mod [BATCH*TD];

// ---------------- helpers ----------------
__device__ __forceinline__ float blockReduceSum256(float v, float* red) {
    int tid = threadIdx.x;
    red[tid] = v;
    __syncthreads();
    #pragma unroll
    for (int s = 128; s > 0; s >>= 1) {
        if (tid < s) red[tid] += red[tid + s];
        __syncthreads();
    }
    return red[0];
}

__device__ __forceinline__ float gelu_tanh(float x) {
    float x3 = x * x * x;
    return 0.5f * x * (1.f + tanhf(0.7978845608028654f * (x + 0.044715f * x3)));
}

__device__ __forceinline__ float to_tf32(float x) {
    unsigned u;
    asm("cvt.rna.tf32.f32 %0, %1;" : "=r"(u) : "f"(x));
    return __uint_as_float(u);
}

__device__ __forceinline__ void mma_tf32(float c[4], float a0, float a1, float a2, float a3,
                                         float b0, float b1) {
    asm volatile(
        "mma.sync.aligned.m16n8k8.row.col.f32.tf32.tf32.f32 "
        "{%0,%1,%2,%3}, {%4,%5,%6,%7}, {%8,%9}, {%0,%1,%2,%3};"
        : "+f"(c[0]), "+f"(c[1]), "+f"(c[2]), "+f"(c[3])
        : "r"(__float_as_uint(a0)), "r"(__float_as_uint(a1)),
          "r"(__float_as_uint(a2)), "r"(__float_as_uint(a3)),
          "r"(__float_as_uint(b0)), "r"(__float_as_uint(b1)));
}

// ---------------- K1: modulation  emb = silu(vec) @ w_mod^T + b_mod ----------------
__global__ void __launch_bounds__(256) mod_kernel(
    const float* __restrict__ vec, const float* __restrict__ wmod,
    const float* __restrict__ bmod)
{
    __shared__ float red[256];
    int o = blockIdx.x;
    int b = o / TD;
    int j = o - b * TD;
    const float* v = vec + b * DMODEL;
    const float* w = wmod + (size_t)j * DMODEL;
    float s = 0.f;
    for (int i = threadIdx.x; i < DMODEL; i += 256) {
        float x = v[i];
        s += (x / (1.f + __expf(-x))) * w[i];
    }
    s = blockReduceSum256(s, red);
    if (threadIdx.x == 0) g_mod[o] = s + bmod[j];
}

// ---------------- K2: concat + RMSNorm (+ optional AdaLN modulate) ----------------
template<bool MOD1>
__global__ void __launch_bounds__(256) norm_kernel(
    const float* __restrict__ txt, const float* __restrict__ img,
    const float* __restrict__ w)
{
    __shared__ float red[256];
    int r = blockIdx.x;
    int b = r / NTOK;
    int n = r - b * NTOK;
    float* xrow = g_x + (size_t)r * DMODEL;
    const float* src;
    if (MOD1) {
        src = (n < LTXT) ? txt + (size_t)(b * LTXT + n) * DMODEL
                         : img + (size_t)(b * NIMG + n - LTXT) * DMODEL;
    } else {
        src = xrow;
    }
    float ss = 0.f;
    for (int i = threadIdx.x; i < DMODEL; i += 256) {
        float v = src[i];
        if (MOD1) xrow[i] = v;
        ss += v * v;
    }
    ss = blockReduceSum256(ss, red);
    float inv = rsqrtf(ss * (1.f / DMODEL) + 1e-6f);
    float* dst = g_xn + (size_t)r * DMODEL;
    if (MOD1) {
        const float* shift = g_mod + b * TD;
        const float* scale = shift + DMODEL;
        for (int i = threadIdx.x; i < DMODEL; i += 256)
            dst[i] = xrow[i] * inv * w[i] * (1.f + scale[i]) + shift[i];
    } else {
        for (int i = threadIdx.x; i < DMODEL; i += 256)
            dst[i] = src[i] * inv * w[i];
    }
}

// ---------------- K3: tf32 tensor-core GEMM  C = A(M,K) @ Bw(Nc,K)^T + epilogue ----------------
// EPI 0: plain store           (qkv)
// EPI 1: gelu(acc + bias)      (fc1)
// EPI 2: res + gate*acc        (out-proj, in-place into g_x)
// EPI 3: acc + bias + res, scatter to split txt/img output (fc2)
// Block tile 128x128, K-tile 16, 8 warps (2x4), warp tile 64x32, mma m16n8k8.
#define SLDA 20   // padded smem row stride (floats) -> conflict-free fragment loads

template<int EPI>
__global__ void __launch_bounds__(256) gemm_tf32_kernel(
    const float* __restrict__ A, const float* __restrict__ Bw,
    float* __restrict__ C, int M, int Nc, int K,
    const float* __restrict__ bias, const float* __restrict__ res,
    const float* __restrict__ modv, float* __restrict__ outp)
{
    __shared__ float As[2][128][SLDA];
    __shared__ float Bs[2][128][SLDA];

    int tid  = threadIdx.x;
    int lane = tid & 31;
    int warp = tid >> 5;
    int wm = warp >> 2;          // 0..1  (64-row slab)
    int wn = warp & 3;           // 0..3  (32-col slab)
    int mBase = blockIdx.y * 128;
    int nBase = blockIdx.x * 128;

    int lrow = tid >> 2;         // 0..63
    int lq   = tid & 3;          // float4 index within 16-float slab

    const float* Ap = A  + (size_t)(mBase + lrow) * K + lq * 4;
    const float* Bp = Bw + (size_t)(nBase + lrow) * K + lq * 4;

    float acc[4][4][4];
    #pragma unroll
    for (int i = 0; i < 4; ++i)
        #pragma unroll
        for (int j = 0; j < 4; ++j)
            #pragma unroll
            for (int r = 0; r < 4; ++r) acc[i][j][r] = 0.f;

    float4 pa0, pa1, pb0, pb1;
    // prefetch slab 0
    pa0 = *(const float4*)(Ap);
    pa1 = *(const float4*)(Ap + 64 * (size_t)K);
    pb0 = *(const float4*)(Bp);
    pb1 = *(const float4*)(Bp + 64 * (size_t)K);

    // store slab 0 (tf32-converted)
    {
        float* d0 = &As[0][lrow][lq * 4];
        d0[0]=to_tf32(pa0.x); d0[1]=to_tf32(pa0.y); d0[2]=to_tf32(pa0.z); d0[3]=to_tf32(pa0.w);
        float* d1 = &As[0][lrow + 64][lq * 4];
        d1[0]=to_tf32(pa1.x); d1[1]=to_tf32(pa1.y); d1[2]=to_tf32(pa1.z); d1[3]=to_tf32(pa1.w);
        float* e0 = &Bs[0][lrow][lq * 4];
        e0[0]=to_tf32(pb0.x); e0[1]=to_tf32(pb0.y); e0[2]=to_tf32(pb0.z); e0[3]=to_tf32(pb0.w);
        float* e1 = &Bs[0][lrow + 64][lq * 4];
        e1[0]=to_tf32(pb1.x); e1[1]=to_tf32(pb1.y); e1[2]=to_tf32(pb1.z); e1[3]=to_tf32(pb1.w);
    }
    __syncthreads();

    int nkt = K >> 4;
    // prefetch slab 1
    if (nkt > 1) {
        pa0 = *(const float4*)(Ap + 16);
        pa1 = *(const float4*)(Ap + 16 + 64 * (size_t)K);
        pb0 = *(const float4*)(Bp + 16);
        pb1 = *(const float4*)(Bp + 16 + 64 * (size_t)K);
    }

    for (int kt = 0; kt < nkt; ++kt) {
        int buf = kt & 1;
        // commit prefetched slab kt+1 into the other buffer (its last readers
        // finished before the sync that ended iteration kt-1)
        if (kt + 1 < nkt) {
            int nb = buf ^ 1;
            float* d0 = &As[nb][lrow][lq * 4];
            d0[0]=to_tf32(pa0.x); d0[1]=to_tf32(pa0.y); d0[2]=to_tf32(pa0.z); d0[3]=to_tf32(pa0.w);
            float* d1 = &As[nb][lrow + 64][lq * 4];
            d1[0]=to_tf32(pa1.x); d1[1]=to_tf32(pa1.y); d1[2]=to_tf32(pa1.z); d1[3]=to_tf32(pa1.w);
            float* e0 = &Bs[nb][lrow][lq * 4];
            e0[0]=to_tf32(pb0.x); e0[1]=to_tf32(pb0.y); e0[2]=to_tf32(pb0.z); e0[3]=to_tf32(pb0.w);
            float* e1 = &Bs[nb][lrow + 64][lq * 4];
            e1[0]=to_tf32(pb1.x); e1[1]=to_tf32(pb1.y); e1[2]=to_tf32(pb1.z); e1[3]=to_tf32(pb1.w);
        }
        // issue global prefetch for slab kt+2 (latency hidden under the mmas)
        if (kt + 2 < nkt) {
            int off = (kt + 2) * 16;
            pa0 = *(const float4*)(Ap + off);
            pa1 = *(const float4*)(Ap + off + 64 * (size_t)K);
            pb0 = *(const float4*)(Bp + off);
            pb1 = *(const float4*)(Bp + off + 64 * (size_t)K);
        }

        // compute on buf: two k8 steps
        #pragma unroll
        for (int ks = 0; ks < 16; ks += 8) {
            float a[4][4], b[4][2];
            int kc = ks + (lane & 3);
            #pragma unroll
            for (int mi = 0; mi < 4; ++mi) {
                int m0 = wm * 64 + mi * 16 + (lane >> 2);
                a[mi][0] = As[buf][m0][kc];
                a[mi][1] = As[buf][m0 + 8][kc];
                a[mi][2] = As[buf][m0][kc + 4];
                a[mi][3] = As[buf][m0 + 8][kc + 4];
            }
            #pragma unroll
            for (int ni = 0; ni < 4; ++ni) {
                int n0 = wn * 32 + ni * 8 + (lane >> 2);
                b[ni][0] = Bs[buf][n0][kc];
                b[ni][1] = Bs[buf][n0][kc + 4];
            }
            #pragma unroll
            for (int mi = 0; mi < 4; ++mi)
                #pragma unroll
                for (int ni = 0; ni < 4; ++ni)
                    mma_tf32(acc[mi][ni], a[mi][0], a[mi][1], a[mi][2], a[mi][3],
                             b[ni][0], b[ni][1]);
        }
        __syncthreads();
    }

    // ---------------- epilogue ----------------
    #pragma unroll
    for (int mi = 0; mi < 4; ++mi) {
        int rbase = mBase + wm * 64 + mi * 16 + (lane >> 2);
        #pragma unroll
        for (int half = 0; half < 2; ++half) {
            int row = rbase + half * 8;
            int b_idx = row / NTOK;
            int n_idx = row - b_idx * NTOK;
            #pragma unroll
            for (int ni = 0; ni < 4; ++ni) {
                int col = nBase + wn * 32 + ni * 8 + (lane & 3) * 2;
                float v0 = acc[mi][ni][half * 2 + 0];
                float v1 = acc[mi][ni][half * 2 + 1];
                if (EPI == 1) {
                    v0 = gelu_tanh(v0 + bias[col]);
                    v1 = gelu_tanh(v1 + bias[col + 1]);
                } else if (EPI == 2) {
                    float g0 = modv[b_idx * TD + 2 * DMODEL + col];
                    float g1 = modv[b_idx * TD + 2 * DMODEL + col + 1];
                    v0 = res[(size_t)row * Nc + col]     + g0 * v0;
                    v1 = res[(size_t)row * Nc + col + 1] + g1 * v1;
                } else if (EPI == 3) {
                    v0 = v0 + bias[col]     + res[(size_t)row * Nc + col];
                    v1 = v1 + bias[col + 1] + res[(size_t)row * Nc + col + 1];
                }
                float2 v = make_float2(v0, v1);
                if (EPI == 3) {
                    float* dst = (n_idx < LTXT)
                        ? outp + ((size_t)(b_idx * LTXT + n_idx) * DMODEL + col)
                        : outp + ((size_t)(BATCH * LTXT * DMODEL)
                                  + (size_t)(b_idx * NIMG + n_idx - LTXT) * DMODEL + col);
                    *(float2*)dst = v;
                } else {
                    *(float2*)&C[(size_t)row * Nc + col] = v;
                }
            }
        }
    }
}

// ---------------- K4: RoPE + transpose qkv -> (B,H,N,DH) q/k/v ----------------
__global__ void __launch_bounds__(64) rope_kernel(const float* __restrict__ img_rope)
{
    int r = blockIdx.x;
    int b = r / NTOK;
    int n = r - b * NTOK;
    int h = blockIdx.y;
    int t = threadIdx.x;

    float cs = 0.f, sn = 0.f;
    if (n >= LTXT) {
        const float* rp = img_rope + (size_t)(b * NIMG + n - LTXT) * DHEAD + 2 * t;
        cs = rp[0]; sn = rp[1];
    }
    const float* row = g_qkv + (size_t)r * TD;
    float2 q = *(const float2*)&row[h * DHEAD + 2 * t];
    float2 k = *(const float2*)&row[DMODEL + h * DHEAD + 2 * t];
    float2 v = *(const float2*)&row[2 * DMODEL + h * DHEAD + 2 * t];

    size_t o = ((size_t)(b * NH + h) * NTOK + n) * DHEAD + 2 * t;
    float2 qo = make_float2(q.x * cs - q.y * sn, q.y * cs + q.x * sn);
    float2 ko = make_float2(k.x * cs - k.y * sn, k.y * cs + k.x * sn);
    *(float2*)&g_q[o] = qo;
    *(float2*)&g_k[o] = ko;
    *(float2*)&g_v[o] = v;
}

// ---------------- K5: flash attention, fp32, 64x64 tiles ----------------
#define BQ  64
#define BKV 64
#define KT_STRIDE 68
#define SS_STRIDE 65
#define ATT_SMEM_FLOATS (BQ*DHEAD + DHEAD*KT_STRIDE + BKV*DHEAD + BQ*SS_STRIDE + 3*BQ)
#define ATT_SMEM_BYTES  (ATT_SMEM_FLOATS * 4)

__global__ void __launch_bounds__(256) attn_kernel()
{
    extern __shared__ float sm[];
    float* Qs   = sm;
    float* Kts  = Qs  + BQ * DHEAD;
    float* Vs   = Kts + DHEAD * KT_STRIDE;
    float* Ss   = Vs  + BKV * DHEAD;
    float* rowm = Ss  + BQ * SS_STRIDE;
    float* rowl = rowm + BQ;
    float* rowc = rowl + BQ;

    int tid = threadIdx.x;
    int bh  = blockIdx.y;
    int b   = bh / NH;
    int h   = bh - b * NH;
    int q0  = blockIdx.x * BQ;

    const float* Qg = g_q + ((size_t)bh * NTOK + q0) * DHEAD;
    const float* Kg = g_k + (size_t)bh * NTOK * DHEAD;
    const float* Vg = g_v + (size_t)bh * NTOK * DHEAD;

    #pragma unroll
    for (int it = 0; it < 8; ++it) {
        int f = it * 256 + tid;
        int n = f >> 5;
        int k4 = (f & 31) * 4;
        *(float4*)&Qs[n * DHEAD + k4] = *(const float4*)&Qg[n * DHEAD + k4];
    }
    if (tid < BQ) { rowm[tid] = -1e30f; rowl[tid] = 0.f; }

    float Oacc[32];
    #pragma unroll
    for (int i = 0; i < 32; ++i) Oacc[i] = 0.f;
    int orow = tid & 63;
    int ocb  = (tid >> 6) * 32;
    int tx = tid & 15, ty = tid >> 4;
    __syncthreads();

    const float scale = 0.08838834764831845f;

    for (int t = 0; t < NTOK / BKV; ++t) {
        const float* Kt = Kg + (size_t)t * BKV * DHEAD;
        const float* Vt = Vg + (size_t)t * BKV * DHEAD;
        #pragma unroll
        for (int it = 0; it < 8; ++it) {
            int f = it * 256 + tid;
            int n = f >> 5;
            int k4 = (f & 31) * 4;
            float4 kv = *(const float4*)&Kt[n * DHEAD + k4];
            Kts[(k4 + 0) * KT_STRIDE + n] = kv.x;
            Kts[(k4 + 1) * KT_STRIDE + n] = kv.y;
            Kts[(k4 + 2) * KT_STRIDE + n] = kv.z;
            Kts[(k4 + 3) * KT_STRIDE + n] = kv.w;
            *(float4*)&Vs[n * DHEAD + k4] = *(const float4*)&Vt[n * DHEAD + k4];
        }
        __syncthreads();

        float s[4][4];
        #pragma unroll
        for (int i = 0; i < 4; ++i)
            #pragma unroll
            for (int j = 0; j < 4; ++j) s[i][j] = 0.f;

        for (int k = 0; k < DHEAD; k += 4) {
            float avr[4][4];
            #pragma unroll
            for (int i = 0; i < 4; ++i) {
                float4 a4 = *(const float4*)&Qs[(ty * 4 + i) * DHEAD + k];
                avr[i][0] = a4.x; avr[i][1] = a4.y; avr[i][2] = a4.z; avr[i][3] = a4.w;
            }
            #pragma unroll
            for (int kk = 0; kk < 4; ++kk) {
                float4 bv = *(const float4*)&Kts[(k + kk) * KT_STRIDE + tx * 4];
                #pragma unroll
                for (int i = 0; i < 4; ++i) {
                    float a = avr[i][kk];
                    s[i][0] = fmaf(a, bv.x, s[i][0]);
                    s[i][1] = fmaf(a, bv.y, s[i][1]);
                    s[i][2] = fmaf(a, bv.z, s[i][2]);
                    s[i][3] = fmaf(a, bv.w, s[i][3]);
                }
            }
        }
        #pragma unroll
        for (int i = 0; i < 4; ++i)
            #pragma unroll
            for (int j = 0; j < 4; ++j)
                Ss[(ty * 4 + i) * SS_STRIDE + tx * 4 + j] = s[i][j] * scale;
        __syncthreads();

        if (tid < BQ) {
            int r = tid;
            float m = rowm[r];
            float mx = m;
            #pragma unroll 8
            for (int j = 0; j < BKV; ++j) mx = fmaxf(mx, Ss[r * SS_STRIDE + j]);
            float c = __expf(m - mx);
            float l = rowl[r] * c;
            #pragma unroll 8
            for (int j = 0; j < BKV; ++j) {
                float p = __expf(Ss[r * SS_STRIDE + j] - mx);
                Ss[r * SS_STRIDE + j] = p;
                l += p;
            }
            rowm[r] = mx; rowl[r] = l; rowc[r] = c;
        }
        __syncthreads();

        float c = rowc[orow];
        #pragma unroll
        for (int i = 0; i < 32; ++i) Oacc[i] *= c;
        for (int j = 0; j < BKV; ++j) {
            float p = Ss[orow * SS_STRIDE + j];
            const float* vrow = &Vs[j * DHEAD + ocb];
            #pragma unroll
            for (int i = 0; i < 32; i += 4) {
                float4 vv = *(const float4*)&vrow[i];
                Oacc[i + 0] = fmaf(p, vv.x, Oacc[i + 0]);
                Oacc[i + 1] = fmaf(p, vv.y, Oacc[i + 1]);
                Oacc[i + 2] = fmaf(p, vv.z, Oacc[i + 2]);
                Oacc[i + 3] = fmaf(p, vv.w, Oacc[i + 3]);
            }
        }
        __syncthreads();
    }

    float inv = 1.f / rowl[orow];
    float* og = g_attn + (size_t)(b * NTOK + q0 + orow) * DMODEL + h * DHEAD + ocb;
    #pragma unroll
    for (int i = 0; i < 32; i += 4) {
        float4 v = make_float4(Oacc[i] * inv, Oacc[i+1] * inv, Oacc[i+2] * inv, Oacc[i+3] * inv);
        *(float4*)&og[i] = v;
    }
}

// ---------------- host launcher ----------------
extern "C" void kernel_launch(void* const* d_in, const int* in_sizes, int n_in,
                              void* d_out, int out_size)
{
    const float* txt      = (const float*)d_in[0];
    const float* img      = (const float*)d_in[1];
    const float* vec      = (const float*)d_in[2];
    const float* img_rope = (const float*)d_in[4];
    const float* w_norm1  = (const float*)d_in[5];
    const float* w_mod    = (const float*)d_in[6];
    const float* b_mod    = (const float*)d_in[7];
    const float* w_qkv    = (const float*)d_in[8];
    const float* w_out    = (const float*)d_in[9];
    const float* w_norm2  = (const float*)d_in[10];
    const float* w_fc1    = (const float*)d_in[11];
    const float* b_fc1    = (const float*)d_in[12];
    const float* w_fc2    = (const float*)d_in[13];
    const float* b_fc2    = (const float*)d_in[14];
    float* out = (float*)d_out;

    float *px, *pxn, *pqkv, *pattn, *ph, *pmod;
    cudaGetSymbolAddress((void**)&px,    g_x);
    cudaGetSymbolAddress((void**)&pxn,   g_xn);
    cudaGetSymbolAddress((void**)&pqkv,  g_qkv);
    cudaGetSymbolAddress((void**)&pattn, g_attn);
    cudaGetSymbolAddress((void**)&ph,    g_h);
    cudaGetSymbolAddress((void**)&pmod,  g_mod);

    // 1. AdaLN modulation vector
    mod_kernel<<<BATCH * TD, 256>>>(vec, w_mod, b_mod);
    // 2. concat + RMSNorm + modulate
    norm_kernel<true><<<ROWS, 256>>>(txt, img, w_norm1);
    // 3. qkv projection (tf32 tensor)
    gemm_tf32_kernel<0><<<dim3(TD / 128, ROWS / 128), 256>>>(
        pxn, w_qkv, pqkv, ROWS, TD, DMODEL, nullptr, nullptr, nullptr, nullptr);
    // 4. RoPE + head transpose
    rope_kernel<<<dim3(ROWS, NH), 64>>>(img_rope);
    // 5. flash attention (fp32)
    cudaFuncSetAttribute(attn_kernel, cudaFuncAttributeMaxDynamicSharedMemorySize,
                         ATT_SMEM_BYTES);
    attn_kernel<<<dim3(NTOK / BQ, BATCH * NH), 256, ATT_SMEM_BYTES>>>();
    // 6. out projection + gated residual
    gemm_tf32_kernel<2><<<dim3(DMODEL / 128, ROWS / 128), 256>>>(
        pattn, w_out, px, ROWS, DMODEL, DMODEL, nullptr, px, pmod, nullptr);
    // 7. RMSNorm 2
    norm_kernel<false><<<ROWS, 256>>>(nullptr, nullptr, w_norm2);
    // 8. fc1 + gelu
    gemm_tf32_kernel<1><<<dim3(MLPH / 128, ROWS / 128), 256>>>(
        pxn, w_fc1, ph, ROWS, MLPH, DMODEL, b_fc1, nullptr, nullptr, nullptr);
    // 9. fc2 + bias + residual, scatter to split output
    gemm_tf32_kernel<3><<<dim3(DMODEL / 128, ROWS / 128), 256>>>(
        ph, w_fc2, nullptr, ROWS, DMODEL, MLPH, b_fc2, px, nullptr, out);
}

// round 6
// speedup vs baseline: 3.4483x; 2.0169x over previous
#include <cuda_runtime.h>
#include <math.h>
#include <stdint.h>

// ---------------- problem constants ----------------
#define BATCH   2
#define LTXT    256
#define NIMG    2048
#define NTOK    2304          // LTXT + NIMG
#define DMODEL  1536
#define NH      12
#define DHEAD   128
#define TD      4608          // 3*DMODEL
#define MLPH    6144
#define ROWS    (BATCH*NTOK)  // 4608

// ---------------- device scratch (no allocs allowed) ----------------
__device__ __align__(128) float g_x   [ROWS*DMODEL];
__device__ __align__(128) float g_xn  [ROWS*DMODEL];
__device__ __align__(128) float g_qkv [ROWS*TD];
__device__ __align__(128) float g_q   [ROWS*DMODEL];
__device__ __align__(128) float g_k   [ROWS*DMODEL];
__device__ __align__(128) float g_v   [ROWS*DMODEL];
__device__ __align__(128) float g_attn[ROWS*DMODEL];
__device__ __align__(128) float g_h   [ROWS*MLPH];
__device__ __align__(128) float g_mod [BATCH*TD];

// ---------------- helpers ----------------
__device__ __forceinline__ float blockReduceSum256(float v, float* red) {
    int tid = threadIdx.x;
    red[tid] = v;
    __syncthreads();
    #pragma unroll
    for (int s = 128; s > 0; s >>= 1) {
        if (tid < s) red[tid] += red[tid + s];
        __syncthreads();
    }
    return red[0];
}

__device__ __forceinline__ float gelu_tanh(float x) {
    float x3 = x * x * x;
    return 0.5f * x * (1.f + tanhf(0.7978845608028654f * (x + 0.044715f * x3)));
}

__device__ __forceinline__ float to_tf32(float x) {
    unsigned u;
    asm("cvt.rna.tf32.f32 %0, %1;" : "=r"(u) : "f"(x));
    return __uint_as_float(u);
}

__device__ __forceinline__ void mma_tf32(float c[4], float a0, float a1, float a2, float a3,
                                         float b0, float b1) {
    asm volatile(
        "mma.sync.aligned.m16n8k8.row.col.f32.tf32.tf32.f32 "
        "{%0,%1,%2,%3}, {%4,%5,%6,%7}, {%8,%9}, {%0,%1,%2,%3};"
        : "+f"(c[0]), "+f"(c[1]), "+f"(c[2]), "+f"(c[3])
        : "r"(__float_as_uint(a0)), "r"(__float_as_uint(a1)),
          "r"(__float_as_uint(a2)), "r"(__float_as_uint(a3)),
          "r"(__float_as_uint(b0)), "r"(__float_as_uint(b1)));
}

__device__ __forceinline__ void cp16(uint32_t dst, const void* src) {
    asm volatile("cp.async.cg.shared.global [%0], [%1], 16;\n" :: "r"(dst), "l"(src));
}
__device__ __forceinline__ void cp_commit() {
    asm volatile("cp.async.commit_group;\n" ::: "memory");
}
__device__ __forceinline__ void cp_wait1() {
    asm volatile("cp.async.wait_group 1;\n" ::: "memory");
}

// ---------------- K1: modulation  emb = silu(vec) @ w_mod^T + b_mod ----------------
__global__ void __launch_bounds__(256) mod_kernel(
    const float* __restrict__ vec, const float* __restrict__ wmod,
    const float* __restrict__ bmod)
{
    __shared__ float red[256];
    int o = blockIdx.x;
    int b = o / TD;
    int j = o - b * TD;
    const float* v = vec + b * DMODEL;
    const float* w = wmod + (size_t)j * DMODEL;
    float s = 0.f;
    for (int i = threadIdx.x; i < DMODEL; i += 256) {
        float x = v[i];
        s += (x / (1.f + __expf(-x))) * w[i];
    }
    s = blockReduceSum256(s, red);
    if (threadIdx.x == 0) g_mod[o] = s + bmod[j];
}

// ---------------- K2: concat + RMSNorm (+ optional AdaLN modulate) ----------------
template<bool MOD1>
__global__ void __launch_bounds__(256) norm_kernel(
    const float* __restrict__ txt, const float* __restrict__ img,
    const float* __restrict__ w)
{
    __shared__ float red[256];
    int r = blockIdx.x;
    int b = r / NTOK;
    int n = r - b * NTOK;
    float* xrow = g_x + (size_t)r * DMODEL;
    const float* src;
    if (MOD1) {
        src = (n < LTXT) ? txt + (size_t)(b * LTXT + n) * DMODEL
                         : img + (size_t)(b * NIMG + n - LTXT) * DMODEL;
    } else {
        src = xrow;
    }
    float ss = 0.f;
    for (int i = threadIdx.x; i < DMODEL; i += 256) {
        float v = src[i];
        if (MOD1) xrow[i] = v;
        ss += v * v;
    }
    ss = blockReduceSum256(ss, red);
    float inv = rsqrtf(ss * (1.f / DMODEL) + 1e-6f);
    float* dst = g_xn + (size_t)r * DMODEL;
    if (MOD1) {
        const float* shift = g_mod + b * TD;
        const float* scale = shift + DMODEL;
        for (int i = threadIdx.x; i < DMODEL; i += 256)
            dst[i] = xrow[i] * inv * w[i] * (1.f + scale[i]) + shift[i];
    } else {
        for (int i = threadIdx.x; i < DMODEL; i += 256)
            dst[i] = src[i] * inv * w[i];
    }
}

// ---------------- K3: tf32 GEMM with cp.async double buffering ----------------
// C = A(M,K) @ Bw(Nc,K)^T + epilogue.  Block 128x128, K-tile 16, 8 warps (2x4),
// warp tile 64x32, mma m16n8k8.  Fragments rna-rounded to tf32 AFTER the LDS
// (cp.async lands raw fp32 in smem; rounding in registers restores accuracy).
#define SLDA 20   // padded smem row stride (floats): fragment LDS conflict-free

template<int EPI>
__global__ void __launch_bounds__(256, 2) gemm_tf32_kernel(
    const float* __restrict__ A, const float* __restrict__ Bw,
    float* __restrict__ C, int M, int Nc, int K,
    const float* __restrict__ bias, const float* __restrict__ res,
    const float* __restrict__ modv, float* __restrict__ outp)
{
    __shared__ __align__(16) float As[2][128][SLDA];
    __shared__ __align__(16) float Bs[2][128][SLDA];

    int tid  = threadIdx.x;
    int lane = tid & 31;
    int warp = tid >> 5;
    int wm = warp >> 2;
    int wn = warp & 3;
    int mBase = blockIdx.y * 128;
    int nBase = blockIdx.x * 128;

    int lrow = tid >> 2;         // 0..63
    int lq   = tid & 3;

    const float* Ap = A  + (size_t)(mBase + lrow) * K + lq * 4;
    const float* Bp = Bw + (size_t)(nBase + lrow) * K + lq * 4;

    uint32_t sA = (uint32_t)__cvta_generic_to_shared(&As[0][0][0]);
    uint32_t sB = (uint32_t)__cvta_generic_to_shared(&Bs[0][0][0]);
    uint32_t dA0 = sA + ((size_t)lrow * SLDA + lq * 4) * 4;
    uint32_t dA1 = sA + ((size_t)(lrow + 64) * SLDA + lq * 4) * 4;
    uint32_t dB0 = sB + ((size_t)lrow * SLDA + lq * 4) * 4;
    uint32_t dB1 = sB + ((size_t)(lrow + 64) * SLDA + lq * 4) * 4;
    const uint32_t bufStep = 128 * SLDA * 4;

    float acc[4][4][4];
    #pragma unroll
    for (int i = 0; i < 4; ++i)
        #pragma unroll
        for (int j = 0; j < 4; ++j)
            #pragma unroll
            for (int r = 0; r < 4; ++r) acc[i][j][r] = 0.f;

    int nkt = K >> 4;

    // stage 0
    cp16(dA0, Ap);               cp16(dA1, Ap + 64 * (size_t)K);
    cp16(dB0, Bp);               cp16(dB1, Bp + 64 * (size_t)K);
    cp_commit();
    // stage 1
    cp16(dA0 + bufStep, Ap + 16);               cp16(dA1 + bufStep, Ap + 16 + 64 * (size_t)K);
    cp16(dB0 + bufStep, Bp + 16);               cp16(dB1 + bufStep, Bp + 16 + 64 * (size_t)K);
    cp_commit();

    for (int kt = 0; kt < nkt; ++kt) {
        int buf = kt & 1;
        cp_wait1();              // tile kt resident
        __syncthreads();

        #pragma unroll
        for (int ks = 0; ks < 16; ks += 8) {
            float a[4][4], b[4][2];
            int kc = ks + (lane & 3);
            #pragma unroll
            for (int mi = 0; mi < 4; ++mi) {
                int m0 = wm * 64 + mi * 16 + (lane >> 2);
                a[mi][0] = to_tf32(As[buf][m0][kc]);
                a[mi][1] = to_tf32(As[buf][m0 + 8][kc]);
                a[mi][2] = to_tf32(As[buf][m0][kc + 4]);
                a[mi][3] = to_tf32(As[buf][m0 + 8][kc + 4]);
            }
            #pragma unroll
            for (int ni = 0; ni < 4; ++ni) {
                int n0 = wn * 32 + ni * 8 + (lane >> 2);
                b[ni][0] = to_tf32(Bs[buf][n0][kc]);
                b[ni][1] = to_tf32(Bs[buf][n0][kc + 4]);
            }
            #pragma unroll
            for (int mi = 0; mi < 4; ++mi)
                #pragma unroll
                for (int ni = 0; ni < 4; ++ni)
                    mma_tf32(acc[mi][ni], a[mi][0], a[mi][1], a[mi][2], a[mi][3],
                             b[ni][0], b[ni][1]);
        }
        __syncthreads();         // all readers of buf done before refilling it

        if (kt + 2 < nkt) {
            int off = (kt + 2) * 16;
            uint32_t bofs = buf * bufStep;   // refill the buffer just consumed
            cp16(dA0 + bofs, Ap + off);             cp16(dA1 + bofs, Ap + off + 64 * (size_t)K);
            cp16(dB0 + bofs, Bp + off);             cp16(dB1 + bofs, Bp + off + 64 * (size_t)K);
        }
        cp_commit();             // always commit (possibly empty) to keep group count
    }

    // ---------------- epilogue ----------------
    #pragma unroll
    for (int mi = 0; mi < 4; ++mi) {
        int rbase = mBase + wm * 64 + mi * 16 + (lane >> 2);
        #pragma unroll
        for (int half = 0; half < 2; ++half) {
            int row = rbase + half * 8;
            int b_idx = row / NTOK;
            int n_idx = row - b_idx * NTOK;
            #pragma unroll
            for (int ni = 0; ni < 4; ++ni) {
                int col = nBase + wn * 32 + ni * 8 + (lane & 3) * 2;
                float v0 = acc[mi][ni][half * 2 + 0];
                float v1 = acc[mi][ni][half * 2 + 1];
                if (EPI == 1) {
                    v0 = gelu_tanh(v0 + bias[col]);
                    v1 = gelu_tanh(v1 + bias[col + 1]);
                } else if (EPI == 2) {
                    float g0 = modv[b_idx * TD + 2 * DMODEL + col];
                    float g1 = modv[b_idx * TD + 2 * DMODEL + col + 1];
                    v0 = res[(size_t)row * Nc + col]     + g0 * v0;
                    v1 = res[(size_t)row * Nc + col + 1] + g1 * v1;
                } else if (EPI == 3) {
                    v0 = v0 + bias[col]     + res[(size_t)row * Nc + col];
                    v1 = v1 + bias[col + 1] + res[(size_t)row * Nc + col + 1];
                }
                float2 v = make_float2(v0, v1);
                if (EPI == 3) {
                    float* dst = (n_idx < LTXT)
                        ? outp + ((size_t)(b_idx * LTXT + n_idx) * DMODEL + col)
                        : outp + ((size_t)(BATCH * LTXT * DMODEL)
                                  + (size_t)(b_idx * NIMG + n_idx - LTXT) * DMODEL + col);
                    *(float2*)dst = v;
                } else {
                    *(float2*)&C[(size_t)row * Nc + col] = v;
                }
            }
        }
    }
}

// ---------------- K4: RoPE + transpose qkv -> (B,H,N,DH) q/k/v ----------------
__global__ void __launch_bounds__(64) rope_kernel(const float* __restrict__ img_rope)
{
    int r = blockIdx.x;
    int b = r / NTOK;
    int n = r - b * NTOK;
    int h = blockIdx.y;
    int t = threadIdx.x;

    float cs = 0.f, sn = 0.f;
    if (n >= LTXT) {
        const float* rp = img_rope + (size_t)(b * NIMG + n - LTXT) * DHEAD + 2 * t;
        cs = rp[0]; sn = rp[1];
    }
    const float* row = g_qkv + (size_t)r * TD;
    float2 q = *(const float2*)&row[h * DHEAD + 2 * t];
    float2 k = *(const float2*)&row[DMODEL + h * DHEAD + 2 * t];
    float2 v = *(const float2*)&row[2 * DMODEL + h * DHEAD + 2 * t];

    size_t o = ((size_t)(b * NH + h) * NTOK + n) * DHEAD + 2 * t;
    float2 qo = make_float2(q.x * cs - q.y * sn, q.y * cs + q.x * sn);
    float2 ko = make_float2(k.x * cs - k.y * sn, k.y * cs + k.x * sn);
    *(float2*)&g_q[o] = qo;
    *(float2*)&g_k[o] = ko;
    *(float2*)&g_v[o] = v;
}

// ---------------- K5: flash attention on tensor cores (tf32 mma) ----------------
// Tile: 128 q-rows x 64 kv.  8 warps.  S phase: warp tile 32x32 (mi=2, ni=4).
// PV phase: warp tile 32x64 (mi=2, ni=8).  All smem strides = 4 mod 32 words
// so fragment LDS are conflict-free.  All operands rna-rounded to tf32.
#define AQ   128
#define AKV  64
#define QSTR 132
#define KSTR 132
#define VSTR 68
#define PSTR 68
#define ATT_SMEM_FLOATS (AQ*QSTR + AKV*KSTR + DHEAD*VSTR + AQ*PSTR + 3*AQ)
#define ATT_SMEM_BYTES  (ATT_SMEM_FLOATS * 4)

__global__ void __launch_bounds__(256) attn_kernel()
{
    extern __shared__ float sm[];
    float* Qs   = sm;                       // [128][132]
    float* Ks   = Qs + AQ * QSTR;           // [64][132]
    float* Vt   = Ks + AKV * KSTR;          // [128][68]  (dh-major, transposed V)
    float* Ps   = Vt + DHEAD * VSTR;        // [128][68]
    float* rowm = Ps + AQ * PSTR;
    float* rowl = rowm + AQ;
    float* rowc = rowl + AQ;

    int tid  = threadIdx.x;
    int lane = tid & 31;
    int warp = tid >> 5;
    int wr = warp & 3;                      // row-block (32 rows each)
    int wc = warp >> 2;                     // col-block
    int bh  = blockIdx.y;
    int b   = bh / NH;
    int h   = bh - b * NH;
    int q0  = blockIdx.x * AQ;

    const float* Qg = g_q + ((size_t)bh * NTOK + q0) * DHEAD;
    const float* Kg = g_k + (size_t)bh * NTOK * DHEAD;
    const float* Vg = g_v + (size_t)bh * NTOK * DHEAD;

    // load Q (tf32-rounded): 128 rows x 32 float4
    #pragma unroll
    for (int it = 0; it < 16; ++it) {
        int f = it * 256 + tid;
        int n = f >> 5;
        int k4 = (f & 31) * 4;
        float4 v = *(const float4*)&Qg[(size_t)n * DHEAD + k4];
        v.x = to_tf32(v.x); v.y = to_tf32(v.y); v.z = to_tf32(v.z); v.w = to_tf32(v.w);
        *(float4*)&Qs[n * QSTR + k4] = v;
    }
    if (tid < AQ) { rowm[tid] = -1e30f; rowl[tid] = 0.f; }

    float accO[2][8][4];
    #pragma unroll
    for (int mi = 0; mi < 2; ++mi)
        #pragma unroll
        for (int ni = 0; ni < 8; ++ni)
            #pragma unroll
            for (int r = 0; r < 4; ++r) accO[mi][ni][r] = 0.f;

    __syncthreads();

    const float scale = 0.08838834764831845f;   // DH^-0.5
    int rows0 = wr * 32;

    for (int t = 0; t < NTOK / AKV; ++t) {
        // load K tile (row-major, [kv][dh]) — it IS the col-major B operand
        #pragma unroll
        for (int it = 0; it < 8; ++it) {
            int f = it * 256 + tid;
            int n = f >> 5;                 // kv row
            int k4 = (f & 31) * 4;
            float4 v = *(const float4*)&Kg[((size_t)t * AKV + n) * DHEAD + k4];
            v.x = to_tf32(v.x); v.y = to_tf32(v.y); v.z = to_tf32(v.z); v.w = to_tf32(v.w);
            *(float4*)&Ks[n * KSTR + k4] = v;
        }
        // load V transposed: Vt[dh][kv]; warp = fixed kq, contiguous n -> no conflicts
        #pragma unroll
        for (int it = 0; it < 8; ++it) {
            int f = it * 256 + tid;
            int kq = f >> 6;                // 0..31  (dh/4)
            int n  = f & 63;                // kv
            float4 v = *(const float4*)&Vg[((size_t)t * AKV + n) * DHEAD + kq * 4];
            Vt[(kq * 4 + 0) * VSTR + n] = to_tf32(v.x);
            Vt[(kq * 4 + 1) * VSTR + n] = to_tf32(v.y);
            Vt[(kq * 4 + 2) * VSTR + n] = to_tf32(v.z);
            Vt[(kq * 4 + 3) * VSTR + n] = to_tf32(v.w);
        }
        __syncthreads();

        // ---- S = Q K^T (warp tile 32x32) ----
        float accS[2][4][4];
        #pragma unroll
        for (int mi = 0; mi < 2; ++mi)
            #pragma unroll
            for (int ni = 0; ni < 4; ++ni)
                #pragma unroll
                for (int r = 0; r < 4; ++r) accS[mi][ni][r] = 0.f;

        #pragma unroll
        for (int k8 = 0; k8 < DHEAD / 8; ++k8) {
            int kc = k8 * 8 + (lane & 3);
            float a[2][4], bb[4][2];
            #pragma unroll
            for (int mi = 0; mi < 2; ++mi) {
                int r = rows0 + mi * 16 + (lane >> 2);
                a[mi][0] = Qs[r * QSTR + kc];
                a[mi][1] = Qs[(r + 8) * QSTR + kc];
                a[mi][2] = Qs[r * QSTR + kc + 4];
                a[mi][3] = Qs[(r + 8) * QSTR + kc + 4];
            }
            #pragma unroll
            for (int ni = 0; ni < 4; ++ni) {
                int n0 = wc * 32 + ni * 8 + (lane >> 2);
                bb[ni][0] = Ks[n0 * KSTR + kc];
                bb[ni][1] = Ks[n0 * KSTR + kc + 4];
            }
            #pragma unroll
            for (int mi = 0; mi < 2; ++mi)
                #pragma unroll
                for (int ni = 0; ni < 4; ++ni)
                    mma_tf32(accS[mi][ni], a[mi][0], a[mi][1], a[mi][2], a[mi][3],
                             bb[ni][0], bb[ni][1]);
        }
        // store scaled S
        #pragma unroll
        for (int mi = 0; mi < 2; ++mi) {
            #pragma unroll
            for (int ni = 0; ni < 4; ++ni) {
                int col = wc * 32 + ni * 8 + 2 * (lane & 3);
                int r0 = rows0 + mi * 16 + (lane >> 2);
                *(float2*)&Ps[r0 * PSTR + col] =
                    make_float2(accS[mi][ni][0] * scale, accS[mi][ni][1] * scale);
                *(float2*)&Ps[(r0 + 8) * PSTR + col] =
                    make_float2(accS[mi][ni][2] * scale, accS[mi][ni][3] * scale);
            }
        }
        __syncthreads();

        // ---- online softmax: one thread per q-row ----
        if (tid < AQ) {
            int r = tid;
            float m = rowm[r];
            float mx = m;
            #pragma unroll 8
            for (int j = 0; j < AKV; ++j) mx = fmaxf(mx, Ps[r * PSTR + j]);
            float c = __expf(m - mx);
            float l = rowl[r] * c;
            #pragma unroll 8
            for (int j = 0; j < AKV; ++j) {
                float p = __expf(Ps[r * PSTR + j] - mx);
                Ps[r * PSTR + j] = to_tf32(p);
                l += p;
            }
            rowm[r] = mx; rowl[r] = l; rowc[r] = c;
        }
        __syncthreads();

        // ---- O = O*c + P @ V (warp tile 32x64) ----
        float c0 = rowc[rows0 + (lane >> 2)];
        float c1 = rowc[rows0 + 8 + (lane >> 2)];
        float c2 = rowc[rows0 + 16 + (lane >> 2)];
        float c3 = rowc[rows0 + 24 + (lane >> 2)];
        #pragma unroll
        for (int ni = 0; ni < 8; ++ni) {
            accO[0][ni][0] *= c0; accO[0][ni][1] *= c0;
            accO[0][ni][2] *= c1; accO[0][ni][3] *= c1;
            accO[1][ni][0] *= c2; accO[1][ni][1] *= c2;
            accO[1][ni][2] *= c3; accO[1][ni][3] *= c3;
        }
        #pragma unroll
        for (int k8 = 0; k8 < AKV / 8; ++k8) {
            int kc = k8 * 8 + (lane & 3);
            float a[2][4], bb[8][2];
            #pragma unroll
            for (int mi = 0; mi < 2; ++mi) {
                int r = rows0 + mi * 16 + (lane >> 2);
                a[mi][0] = Ps[r * PSTR + kc];
                a[mi][1] = Ps[(r + 8) * PSTR + kc];
                a[mi][2] = Ps[r * PSTR + kc + 4];
                a[mi][3] = Ps[(r + 8) * PSTR + kc + 4];
            }
            #pragma unroll
            for (int ni = 0; ni < 8; ++ni) {
                int n0 = wc * 64 + ni * 8 + (lane >> 2);   // dh column
                bb[ni][0] = Vt[n0 * VSTR + kc];
                bb[ni][1] = Vt[n0 * VSTR + kc + 4];
            }
            #pragma unroll
            for (int mi = 0; mi < 2; ++mi)
                #pragma unroll
                for (int ni = 0; ni < 8; ++ni)
                    mma_tf32(accO[mi][ni], a[mi][0], a[mi][1], a[mi][2], a[mi][3],
                             bb[ni][0], bb[ni][1]);
        }
        __syncthreads();     // before next tile overwrites Ks/Vt/Ps
    }

    // ---- final: divide by l, write out ----
    float i0 = 1.f / rowl[rows0 + (lane >> 2)];
    float i1 = 1.f / rowl[rows0 + 8 + (lane >> 2)];
    float i2 = 1.f / rowl[rows0 + 16 + (lane >> 2)];
    float i3 = 1.f / rowl[rows0 + 24 + (lane >> 2)];
    #pragma unroll
    for (int mi = 0; mi < 2; ++mi) {
        int r0 = rows0 + mi * 16 + (lane >> 2);
        float ia = (mi == 0) ? i0 : i2;
        float ib = (mi == 0) ? i1 : i3;
        #pragma unroll
        for (int ni = 0; ni < 8; ++ni) {
            int col = h * DHEAD + wc * 64 + ni * 8 + 2 * (lane & 3);
            float* d0 = &g_attn[(size_t)(b * NTOK + q0 + r0) * DMODEL + col];
            float* d1 = &g_attn[(size_t)(b * NTOK + q0 + r0 + 8) * DMODEL + col];
            *(float2*)d0 = make_float2(accO[mi][ni][0] * ia, accO[mi][ni][1] * ia);
            *(float2*)d1 = make_float2(accO[mi][ni][2] * ib, accO[mi][ni][3] * ib);
        }
    }
}

// ---------------- host launcher ----------------
extern "C" void kernel_launch(void* const* d_in, const int* in_sizes, int n_in,
                              void* d_out, int out_size)
{
    const float* txt      = (const float*)d_in[0];
    const float* img      = (const float*)d_in[1];
    const float* vec      = (const float*)d_in[2];
    const float* img_rope = (const float*)d_in[4];
    const float* w_norm1  = (const float*)d_in[5];
    const float* w_mod    = (const float*)d_in[6];
    const float* b_mod    = (const float*)d_in[7];
    const float* w_qkv    = (const float*)d_in[8];
    const float* w_out    = (const float*)d_in[9];
    const float* w_norm2  = (const float*)d_in[10];
    const float* w_fc1    = (const float*)d_in[11];
    const float* b_fc1    = (const float*)d_in[12];
    const float* w_fc2    = (const float*)d_in[13];
    const float* b_fc2    = (const float*)d_in[14];
    float* out = (float*)d_out;

    float *px, *pxn, *pqkv, *pattn, *ph, *pmod;
    cudaGetSymbolAddress((void**)&px,    g_x);
    cudaGetSymbolAddress((void**)&pxn,   g_xn);
    cudaGetSymbolAddress((void**)&pqkv,  g_qkv);
    cudaGetSymbolAddress((void**)&pattn, g_attn);
    cudaGetSymbolAddress((void**)&ph,    g_h);
    cudaGetSymbolAddress((void**)&pmod,  g_mod);

    // 1. AdaLN modulation vector
    mod_kernel<<<BATCH * TD, 256>>>(vec, w_mod, b_mod);
    // 2. concat + RMSNorm + modulate
    norm_kernel<true><<<ROWS, 256>>>(txt, img, w_norm1);
    // 3. qkv projection
    gemm_tf32_kernel<0><<<dim3(TD / 128, ROWS / 128), 256>>>(
        pxn, w_qkv, pqkv, ROWS, TD, DMODEL, nullptr, nullptr, nullptr, nullptr);
    // 4. RoPE + head transpose
    rope_kernel<<<dim3(ROWS, NH), 64>>>(img_rope);
    // 5. flash attention (tf32 tensor)
    cudaFuncSetAttribute(attn_kernel, cudaFuncAttributeMaxDynamicSharedMemorySize,
                         ATT_SMEM_BYTES);
    attn_kernel<<<dim3(NTOK / AQ, BATCH * NH), 256, ATT_SMEM_BYTES>>>();
    // 6. out projection + gated residual
    gemm_tf32_kernel<2><<<dim3(DMODEL / 128, ROWS / 128), 256>>>(
        pattn, w_out, px, ROWS, DMODEL, DMODEL, nullptr, px, pmod, nullptr);
    // 7. RMSNorm 2
    norm_kernel<false><<<ROWS, 256>>>(nullptr, nullptr, w_norm2);
    // 8. fc1 + gelu
    gemm_tf32_kernel<1><<<dim3(MLPH / 128, ROWS / 128), 256>>>(
        pxn, w_fc1, ph, ROWS, MLPH, DMODEL, b_fc1, nullptr, nullptr, nullptr);
    // 9. fc2 + bias + residual, scatter to split output
    gemm_tf32_kernel<3><<<dim3(DMODEL / 128, ROWS / 128), 256>>>(
        ph, w_fc2, nullptr, ROWS, DMODEL, MLPH, b_fc2, px, nullptr, out);
}